// round 5
// baseline (speedup 1.0000x reference)
#include <cuda_runtime.h>
#include <cstdint>

#define NN 100000
#define NE 3200000
#define FIN 512
#define H   16
#define FOUT 128
#define NC  3

// ---------------- scratch (no allocations allowed) ----------------
__device__ float4 g_P1[NN * 4];    // layer-1 projected (pre-agg), 16 f/node, row = 64B
__device__ float4 g_P2[NN * 4];    // relu(...)*norm_src for layer 2
__device__ int    g_deg_out[NN];
__device__ int    g_deg_in[NN];
__device__ int    g_off[NN];       // exclusive prefix sum of deg_in
__device__ int    g_cursor[NN];    // bucket write cursors
__device__ int    g_csr_src[NE];   // src ids grouped by dst
__device__ float  g_Wc[H * NC];    // W2 @ Wfc  (16x3)
__device__ float  g_bc[NC];        // b2 @ Wfc + bfc
__device__ int    g_is64;

// ---------------- f32x2 packed math helpers ----------------
typedef unsigned long long u64;

__device__ __forceinline__ u64 pack2(float a, float b) {
    u64 r; asm("mov.b64 %0, {%1, %2};" : "=l"(r) : "f"(a), "f"(b)); return r;
}
__device__ __forceinline__ void unpack2(u64 v, float& a, float& b) {
    asm("mov.b64 {%0, %1}, %2;" : "=f"(a), "=f"(b) : "l"(v));
}
__device__ __forceinline__ u64 fma2(u64 a, u64 b, u64 c) {
    u64 d; asm("fma.rn.f32x2 %0, %1, %2, %3;" : "=l"(d) : "l"(a), "l"(b), "l"(c)); return d;
}
__device__ __forceinline__ u64 add2(u64 a, u64 b) {
    u64 d; asm("add.rn.f32x2 %0, %1, %2;" : "=l"(d) : "l"(a), "l"(b)); return d;
}
__device__ __forceinline__ u64 mul2(u64 a, u64 b) {
    u64 d; asm("mul.rn.f32x2 %0, %1, %2;" : "=l"(d) : "l"(a), "l"(b)); return d;
}

__device__ __forceinline__ int eidx(const void* p, int e, int is64) {
    if (is64) return (int)__ldcs(((const long long*)p) + e);
    return __ldcs(((const int*)p) + e);
}

// ---------------- index dtype detection ----------------
__global__ void k_detect(const unsigned* __restrict__ w) {
    if (threadIdx.x == 0) {
        int is64 = 1;
        #pragma unroll 1
        for (int i = 0; i < 256; i++) {
            if (w[2 * i + 1] != 0u) { is64 = 0; break; }
        }
        g_is64 = is64;
    }
}

// ---------------- fused W2@Wfc ----------------
__global__ void k_wc(const float* __restrict__ W2, const float* __restrict__ b2,
                     const float* __restrict__ Wfc, const float* __restrict__ bfc) {
    int t = threadIdx.x;
    if (t < H * NC) {
        int k = t / NC, c = t % NC;
        float s = 0.f;
        #pragma unroll 4
        for (int j = 0; j < FOUT; j++) s += W2[k * FOUT + j] * Wfc[j * NC + c];
        g_Wc[t] = s;
    }
    if (t < NC) {
        float s = bfc[t];
        #pragma unroll 4
        for (int j = 0; j < FOUT; j++) s += b2[j] * Wfc[j * NC + t];
        g_bc[t] = s;
    }
}

// ---------------- degrees ----------------
__global__ void k_zero_deg() {
    int i = blockIdx.x * blockDim.x + threadIdx.x;
    if (i < NN) { g_deg_out[i] = 0; g_deg_in[i] = 0; }
}

__global__ void k_degree(const void* __restrict__ src, const void* __restrict__ dst) {
    int e = blockIdx.x * blockDim.x + threadIdx.x;
    if (e >= NE) return;
    int is64 = g_is64;
    atomicAdd(&g_deg_out[eidx(src, e, is64)], 1);
    atomicAdd(&g_deg_in[eidx(dst, e, is64)], 1);
}

// ---------------- exclusive scan of deg_in (single block) ----------------
__global__ void __launch_bounds__(1024) k_scan() {
    __shared__ int part[1024];
    const int CH = (NN + 1023) / 1024;  // 98
    int t = threadIdx.x;
    int base = t * CH;
    int s = 0;
    for (int i = 0; i < CH; i++) {
        int idx = base + i;
        if (idx < NN) s += g_deg_in[idx];
    }
    part[t] = s;
    __syncthreads();
    for (int off = 1; off < 1024; off <<= 1) {
        int v = (t >= off) ? part[t - off] : 0;
        __syncthreads();
        part[t] += v;
        __syncthreads();
    }
    int ex = (t > 0) ? part[t - 1] : 0;
    for (int i = 0; i < CH; i++) {
        int idx = base + i;
        if (idx < NN) {
            g_off[idx] = ex;
            g_cursor[idx] = ex;
            ex += g_deg_in[idx];
        }
    }
}

// ---------------- bucket edges by dst ----------------
__global__ void k_bucket(const void* __restrict__ src, const void* __restrict__ dst) {
    int e = blockIdx.x * blockDim.x + threadIdx.x;
    if (e >= NE) return;
    int is64 = g_is64;
    int s = eidx(src, e, is64);
    int d = eidx(dst, e, is64);
    int p = atomicAdd(&g_cursor[d], 1);
    g_csr_src[p] = s;
}

// ---------------- layer-1 GEMM: P1 = norm_src * (feat @ W1) ----------------
__global__ void __launch_bounds__(256) k_gemm1(const float* __restrict__ feat,
                                               const float* __restrict__ W1) {
    __shared__ float2 Wp[8 * FIN];  // [kk][i]
    for (int t = threadIdx.x; t < FIN * 8; t += 256) {
        int i = t >> 3, kk = t & 7;
        Wp[kk * FIN + i] = ((const float2*)W1)[t];  // (W1[i][2kk], W1[i][2kk+1])
    }
    __syncthreads();
    const u64* WpU = (const u64*)Wp;

    int warp = threadIdx.x >> 5, lane = threadIdx.x & 31;
    int row0 = (blockIdx.x * 8 + warp) * 4;
    if (row0 >= NN) return;

    u64 acc[4][8];
    #pragma unroll
    for (int r = 0; r < 4; r++)
        #pragma unroll
        for (int kk = 0; kk < 8; kk++) acc[r][kk] = 0ull;

    #pragma unroll
    for (int m = 0; m < 16; m++) {
        int i = lane + 32 * m;
        u64 wk[8];
        #pragma unroll
        for (int kk = 0; kk < 8; kk++) wk[kk] = WpU[kk * FIN + i];
        #pragma unroll
        for (int r = 0; r < 4; r++) {
            int row = row0 + r;
            float xv = (row < NN) ? __ldcs(feat + (size_t)row * FIN + i) : 0.f;
            u64 xx = pack2(xv, xv);
            #pragma unroll
            for (int kk = 0; kk < 8; kk++) acc[r][kk] = fma2(xx, wk[kk], acc[r][kk]);
        }
    }

    #pragma unroll
    for (int r = 0; r < 4; r++)
        #pragma unroll
        for (int kk = 0; kk < 8; kk++)
            #pragma unroll
            for (int off = 16; off > 0; off >>= 1)
                acc[r][kk] = add2(acc[r][kk], __shfl_xor_sync(0xffffffffu, acc[r][kk], off));

    if (lane == 0) {
        #pragma unroll
        for (int r = 0; r < 4; r++) {
            int row = row0 + r;
            if (row >= NN) break;
            float ns = rsqrtf(fmaxf((float)g_deg_out[row], 1.f));
            u64 nsp = pack2(ns, ns);
            #pragma unroll
            for (int c = 0; c < 4; c++) {
                float a, b, cc, d;
                unpack2(mul2(acc[r][2 * c + 0], nsp), a, b);
                unpack2(mul2(acc[r][2 * c + 1], nsp), cc, d);
                g_P1[row * 4 + c] = make_float4(a, b, cc, d);
            }
        }
    }
}

// ---------------- gather passes: warp per node, high-MLP -------------
// Batch of 32 edges: ONE coalesced index load (lane e), then shfl-broadcast
// and issue 4 independent 16B P-loads per lane (lane = 4*e_slot + q).
// All P loads in a batch are independent -> MLP=4/lane after a single L2 idx trip.
template <int PASS>
__global__ void __launch_bounds__(256) k_gather(const float* __restrict__ b1,
                                                float* __restrict__ out) {
    int warp = threadIdx.x >> 5, lane = threadIdx.x & 31;
    int n = blockIdx.x * 8 + warp;
    if (n >= NN) return;

    int base = g_off[n];
    int deg = g_deg_in[n];
    int e_slot = lane >> 2;
    int q = lane & 3;

    const ulonglong2* P = (PASS == 1) ? (const ulonglong2*)g_P1 : (const ulonglong2*)g_P2;

    u64 acc0 = 0ull, acc1 = 0ull;
    for (int b = 0; b < deg; b += 32) {
        int idx = (b + lane < deg) ? __ldg(g_csr_src + base + b + lane) : -1;
        #pragma unroll
        for (int g = 0; g < 4; g++) {
            int s = __shfl_sync(0xffffffffu, idx, g * 8 + e_slot);
            if (s >= 0) {
                ulonglong2 v = __ldg(P + (size_t)s * 4 + q);
                acc0 = add2(acc0, v.x);
                acc1 = add2(acc1, v.y);
            }
        }
    }
    // reduce across the 8 edge slots (lanes differing in bits 2..4)
    #pragma unroll
    for (int off = 4; off < 32; off <<= 1) {
        acc0 = add2(acc0, __shfl_xor_sync(0xffffffffu, acc0, off));
        acc1 = add2(acc1, __shfl_xor_sync(0xffffffffu, acc1, off));
    }

    float nd = rsqrtf(fmaxf((float)deg, 1.f));
    float a0, a1, a2, a3;
    unpack2(acc0, a0, a1);
    unpack2(acc1, a2, a3);

    if (PASS == 1) {
        float ns = rsqrtf(fmaxf((float)g_deg_out[n], 1.f));
        float4 bb = ((const float4*)b1)[q];
        float4 o;
        o.x = fmaxf(fmaf(a0, nd, bb.x), 0.f) * ns;
        o.y = fmaxf(fmaf(a1, nd, bb.y), 0.f) * ns;
        o.z = fmaxf(fmaf(a2, nd, bb.z), 0.f) * ns;
        o.w = fmaxf(fmaf(a3, nd, bb.w), 0.f) * ns;
        if (lane < 4) g_P2[n * 4 + q] = o;
    } else {
        float z0 = a0 * nd, z1 = a1 * nd, z2 = a2 * nd, z3 = a3 * nd;
        float o[NC];
        #pragma unroll
        for (int c = 0; c < NC; c++) {
            o[c] = z0 * g_Wc[(4 * q + 0) * NC + c] + z1 * g_Wc[(4 * q + 1) * NC + c]
                 + z2 * g_Wc[(4 * q + 2) * NC + c] + z3 * g_Wc[(4 * q + 3) * NC + c];
        }
        #pragma unroll
        for (int c = 0; c < NC; c++) {
            o[c] += __shfl_xor_sync(0xffffffffu, o[c], 1);
            o[c] += __shfl_xor_sync(0xffffffffu, o[c], 2);
        }
        if (lane == 0) {
            out[n * 3 + 0] = o[0] + g_bc[0];
            out[n * 3 + 1] = o[1] + g_bc[1];
            out[n * 3 + 2] = o[2] + g_bc[2];
        }
    }
}

// ---------------- launch ----------------
extern "C" void kernel_launch(void* const* d_in, const int* in_sizes, int n_in,
                              void* d_out, int out_size) {
    const float* features = (const float*)d_in[0];
    const void*  src      = d_in[1];
    const void*  dst      = d_in[2];
    const float* W1       = (const float*)d_in[3];
    const float* b1       = (const float*)d_in[4];
    const float* W2       = (const float*)d_in[5];
    const float* b2       = (const float*)d_in[6];
    const float* Wfc      = (const float*)d_in[7];
    const float* bfc      = (const float*)d_in[8];
    float* out = (float*)d_out;

    (void)in_sizes; (void)n_in; (void)out_size;

    const int EB = (NE + 255) / 256;
    const int NB = (NN + 255) / 256;
    const int GB = (NN + 7) / 8;  // gather: 8 warps/block, warp per node

    k_wc<<<1, 64>>>(W2, b2, Wfc, bfc);
    k_detect<<<1, 32>>>((const unsigned*)src);
    k_zero_deg<<<NB, 256>>>();
    k_degree<<<EB, 256>>>(src, dst);
    k_scan<<<1, 1024>>>();
    k_bucket<<<EB, 256>>>(src, dst);
    k_gemm1<<<(NN + 31) / 32, 256>>>(features, W1);
    k_gather<1><<<GB, 256>>>(b1, out);
    k_gather<2><<<GB, 256>>>(b1, out);
}

// round 6
// speedup vs baseline: 1.5410x; 1.5410x over previous
#include <cuda_runtime.h>
#include <cstdint>

#define NN 100000
#define NE 3200000
#define FIN 512
#define H   16
#define FOUT 128
#define NC  3

// ---------------- scratch (no allocations allowed) ----------------
__device__ float4 g_P1[NN * 4];    // layer-1 projected (pre-agg, * norm_src), 16 f/node
__device__ float4 g_agg1[NN * 4];  // layer-1 aggregation target
__device__ float4 g_Q2[NN];        // (relu(...)*ns) @ Wc : 3 floats + pad per node
__device__ float4 g_agg2[NN];      // layer-2 aggregation target (3 floats + pad)
__device__ int    g_deg_out[NN];
__device__ int    g_deg_in[NN];
__device__ float  g_Wc[H * NC];    // W2 @ Wfc  (16x3)
__device__ float  g_bc[NC];        // b2 @ Wfc + bfc
__device__ int    g_is64;

// ---------------- f32x2 packed math helpers ----------------
typedef unsigned long long u64;

__device__ __forceinline__ u64 pack2(float a, float b) {
    u64 r; asm("mov.b64 %0, {%1, %2};" : "=l"(r) : "f"(a), "f"(b)); return r;
}
__device__ __forceinline__ void unpack2(u64 v, float& a, float& b) {
    asm("mov.b64 {%0, %1}, %2;" : "=f"(a), "=f"(b) : "l"(v));
}
__device__ __forceinline__ u64 fma2(u64 a, u64 b, u64 c) {
    u64 d; asm("fma.rn.f32x2 %0, %1, %2, %3;" : "=l"(d) : "l"(a), "l"(b), "l"(c)); return d;
}
__device__ __forceinline__ u64 add2(u64 a, u64 b) {
    u64 d; asm("add.rn.f32x2 %0, %1, %2;" : "=l"(d) : "l"(a), "l"(b)); return d;
}
__device__ __forceinline__ u64 mul2(u64 a, u64 b) {
    u64 d; asm("mul.rn.f32x2 %0, %1, %2;" : "=l"(d) : "l"(a), "l"(b)); return d;
}

__device__ __forceinline__ int eidx(const void* p, int e, int is64) {
    if (is64) return (int)__ldcs(((const long long*)p) + e);
    return __ldcs(((const int*)p) + e);
}

__device__ __forceinline__ void red_v4(float4* addr, float x, float y, float z, float w) {
    asm volatile("red.global.add.v4.f32 [%0], {%1, %2, %3, %4};"
                 :: "l"(addr), "f"(x), "f"(y), "f"(z), "f"(w) : "memory");
}

// ---------------- index dtype detection ----------------
__global__ void k_detect(const unsigned* __restrict__ w) {
    if (threadIdx.x == 0) {
        int is64 = 1;
        #pragma unroll 1
        for (int i = 0; i < 256; i++) {
            if (w[2 * i + 1] != 0u) { is64 = 0; break; }
        }
        g_is64 = is64;
    }
}

// ---------------- fused W2@Wfc ----------------
__global__ void k_wc(const float* __restrict__ W2, const float* __restrict__ b2,
                     const float* __restrict__ Wfc, const float* __restrict__ bfc) {
    int t = threadIdx.x;
    if (t < H * NC) {
        int k = t / NC, c = t % NC;
        float s = 0.f;
        #pragma unroll 4
        for (int j = 0; j < FOUT; j++) s += W2[k * FOUT + j] * Wfc[j * NC + c];
        g_Wc[t] = s;
    }
    if (t < NC) {
        float s = bfc[t];
        #pragma unroll 4
        for (int j = 0; j < FOUT; j++) s += b2[j] * Wfc[j * NC + t];
        g_bc[t] = s;
    }
}

// ---------------- degrees ----------------
__global__ void k_zero_deg() {
    int i = blockIdx.x * blockDim.x + threadIdx.x;
    if (i < NN) { g_deg_out[i] = 0; g_deg_in[i] = 0; }
}

__global__ void k_degree(const void* __restrict__ src, const void* __restrict__ dst) {
    int e = blockIdx.x * blockDim.x + threadIdx.x;
    if (e >= NE) return;
    int is64 = g_is64;
    atomicAdd(&g_deg_out[eidx(src, e, is64)], 1);
    atomicAdd(&g_deg_in[eidx(dst, e, is64)], 1);
}

// ---------------- layer-1 GEMM: P1 = norm_src * (feat @ W1); zero agg1 -------
__global__ void __launch_bounds__(256) k_gemm1(const float* __restrict__ feat,
                                               const float* __restrict__ W1) {
    __shared__ float2 Wp[8 * FIN];  // [kk][i]
    for (int t = threadIdx.x; t < FIN * 8; t += 256) {
        int i = t >> 3, kk = t & 7;
        Wp[kk * FIN + i] = ((const float2*)W1)[t];  // (W1[i][2kk], W1[i][2kk+1])
    }
    __syncthreads();
    const u64* WpU = (const u64*)Wp;

    int warp = threadIdx.x >> 5, lane = threadIdx.x & 31;
    int row0 = (blockIdx.x * 8 + warp) * 4;
    if (row0 >= NN) return;

    u64 acc[4][8];
    #pragma unroll
    for (int r = 0; r < 4; r++)
        #pragma unroll
        for (int kk = 0; kk < 8; kk++) acc[r][kk] = 0ull;

    #pragma unroll
    for (int m = 0; m < 16; m++) {
        int i = lane + 32 * m;
        u64 wk[8];
        #pragma unroll
        for (int kk = 0; kk < 8; kk++) wk[kk] = WpU[kk * FIN + i];
        #pragma unroll
        for (int r = 0; r < 4; r++) {
            int row = row0 + r;
            float xv = (row < NN) ? __ldcs(feat + (size_t)row * FIN + i) : 0.f;
            u64 xx = pack2(xv, xv);
            #pragma unroll
            for (int kk = 0; kk < 8; kk++) acc[r][kk] = fma2(xx, wk[kk], acc[r][kk]);
        }
    }

    #pragma unroll
    for (int r = 0; r < 4; r++)
        #pragma unroll
        for (int kk = 0; kk < 8; kk++)
            #pragma unroll
            for (int off = 16; off > 0; off >>= 1)
                acc[r][kk] = add2(acc[r][kk], __shfl_xor_sync(0xffffffffu, acc[r][kk], off));

    if (lane == 0) {
        #pragma unroll
        for (int r = 0; r < 4; r++) {
            int row = row0 + r;
            if (row >= NN) break;
            float ns = rsqrtf(fmaxf((float)g_deg_out[row], 1.f));
            u64 nsp = pack2(ns, ns);
            #pragma unroll
            for (int c = 0; c < 4; c++) {
                float a, b, cc, d;
                unpack2(mul2(acc[r][2 * c + 0], nsp), a, b);
                unpack2(mul2(acc[r][2 * c + 1], nsp), cc, d);
                g_P1[row * 4 + c] = make_float4(a, b, cc, d);
                g_agg1[row * 4 + c] = make_float4(0.f, 0.f, 0.f, 0.f);
            }
        }
    }
}

// ---------------- scatter pass 1: agg1[dst] += P1[src] (16 floats) -----------
__global__ void __launch_bounds__(256) k_scatter1(const void* __restrict__ src,
                                                  const void* __restrict__ dst) {
    int e = blockIdx.x * blockDim.x + threadIdx.x;
    if (e >= NE) return;
    int is64 = g_is64;
    int s = eidx(src, e, is64);
    int d = eidx(dst, e, is64);
    const float4* ps = (const float4*)g_P1 + s * 4;
    float4*       pd = g_agg1 + d * 4;
    #pragma unroll
    for (int c = 0; c < 4; c++) {
        float4 v = __ldg(ps + c);
        red_v4(pd + c, v.x, v.y, v.z, v.w);
    }
}

// ---------------- mid: Q2 = (relu(agg1*nd + b1)*ns) @ Wc ; zero agg2 ---------
__global__ void k_mid(const float* __restrict__ b1) {
    int n = blockIdx.x * blockDim.x + threadIdx.x;
    if (n >= NN) return;
    float nd = rsqrtf(fmaxf((float)g_deg_in[n], 1.f));
    float ns = rsqrtf(fmaxf((float)g_deg_out[n], 1.f));
    float o0 = 0.f, o1 = 0.f, o2 = 0.f;
    #pragma unroll
    for (int c = 0; c < 4; c++) {
        float4 a = g_agg1[n * 4 + c];
        float4 b = ((const float4*)b1)[c];
        float h0 = fmaxf(fmaf(a.x, nd, b.x), 0.f) * ns;
        float h1 = fmaxf(fmaf(a.y, nd, b.y), 0.f) * ns;
        float h2 = fmaxf(fmaf(a.z, nd, b.z), 0.f) * ns;
        float h3 = fmaxf(fmaf(a.w, nd, b.w), 0.f) * ns;
        int k = 4 * c;
        o0 = fmaf(h0, g_Wc[(k+0)*NC+0], fmaf(h1, g_Wc[(k+1)*NC+0],
             fmaf(h2, g_Wc[(k+2)*NC+0], fmaf(h3, g_Wc[(k+3)*NC+0], o0))));
        o1 = fmaf(h0, g_Wc[(k+0)*NC+1], fmaf(h1, g_Wc[(k+1)*NC+1],
             fmaf(h2, g_Wc[(k+2)*NC+1], fmaf(h3, g_Wc[(k+3)*NC+1], o1))));
        o2 = fmaf(h0, g_Wc[(k+0)*NC+2], fmaf(h1, g_Wc[(k+1)*NC+2],
             fmaf(h2, g_Wc[(k+2)*NC+2], fmaf(h3, g_Wc[(k+3)*NC+2], o2))));
    }
    g_Q2[n] = make_float4(o0, o1, o2, 0.f);
    g_agg2[n] = make_float4(0.f, 0.f, 0.f, 0.f);
}

// ---------------- scatter pass 2: agg2[dst] += Q2[src]  (ONE v4 RED/edge) ----
__global__ void __launch_bounds__(256) k_scatter2(const void* __restrict__ src,
                                                  const void* __restrict__ dst) {
    int e = blockIdx.x * blockDim.x + threadIdx.x;
    if (e >= NE) return;
    int is64 = g_is64;
    int s = eidx(src, e, is64);
    int d = eidx(dst, e, is64);
    float4 v = __ldg(g_Q2 + s);
    red_v4(g_agg2 + d, v.x, v.y, v.z, v.w);
}

// ---------------- final: out = nd * agg2 + bc -------------------------------
__global__ void k_final(float* __restrict__ out) {
    int n = blockIdx.x * blockDim.x + threadIdx.x;
    if (n >= NN) return;
    float nd = rsqrtf(fmaxf((float)g_deg_in[n], 1.f));
    float4 a = g_agg2[n];
    out[n * 3 + 0] = fmaf(a.x, nd, g_bc[0]);
    out[n * 3 + 1] = fmaf(a.y, nd, g_bc[1]);
    out[n * 3 + 2] = fmaf(a.z, nd, g_bc[2]);
}

// ---------------- launch ----------------
extern "C" void kernel_launch(void* const* d_in, const int* in_sizes, int n_in,
                              void* d_out, int out_size) {
    const float* features = (const float*)d_in[0];
    const void*  src      = d_in[1];
    const void*  dst      = d_in[2];
    const float* W1       = (const float*)d_in[3];
    const float* b1       = (const float*)d_in[4];
    const float* W2       = (const float*)d_in[5];
    const float* b2       = (const float*)d_in[6];
    const float* Wfc      = (const float*)d_in[7];
    const float* bfc      = (const float*)d_in[8];
    float* out = (float*)d_out;

    (void)in_sizes; (void)n_in; (void)out_size;

    const int EB = (NE + 255) / 256;
    const int NB = (NN + 255) / 256;

    k_wc<<<1, 64>>>(W2, b2, Wfc, bfc);
    k_detect<<<1, 32>>>((const unsigned*)src);
    k_zero_deg<<<NB, 256>>>();
    k_degree<<<EB, 256>>>(src, dst);
    k_gemm1<<<(NN + 31) / 32, 256>>>(features, W1);
    k_scatter1<<<EB, 256>>>(src, dst);
    k_mid<<<NB, 256>>>(b1);
    k_scatter2<<<EB, 256>>>(src, dst);
    k_final<<<NB, 256>>>(out);
}

// round 7
// speedup vs baseline: 1.5586x; 1.0114x over previous
#include <cuda_runtime.h>
#include <cstdint>

#define NN 100000
#define NE 3200000
#define FIN 512
#define H   16
#define FOUT 128
#define NC  3

// ---------------- scratch (no allocations allowed) ----------------
__device__ float4 g_P1[NN * 4];    // layer-1 projected (pre-agg, * norm_src), 16 f/node
__device__ float4 g_agg1[NN * 4];  // layer-1 aggregation target
__device__ float4 g_Q2[NN];        // (relu(...)*ns) @ Wc : 3 floats + pad per node
__device__ float4 g_agg2[NN];      // layer-2 aggregation target (3 floats + pad)
__device__ int    g_deg_out[NN];
__device__ int    g_deg_in[NN];
__device__ float  g_Wc[H * NC];    // W2 @ Wfc  (16x3)
__device__ float  g_bc[NC];        // b2 @ Wfc + bfc
__device__ int    g_is64;

// ---------------- f32x2 packed math helpers ----------------
typedef unsigned long long u64;

__device__ __forceinline__ u64 pack2(float a, float b) {
    u64 r; asm("mov.b64 %0, {%1, %2};" : "=l"(r) : "f"(a), "f"(b)); return r;
}
__device__ __forceinline__ void unpack2(u64 v, float& a, float& b) {
    asm("mov.b64 {%0, %1}, %2;" : "=f"(a), "=f"(b) : "l"(v));
}
__device__ __forceinline__ u64 fma2(u64 a, u64 b, u64 c) {
    u64 d; asm("fma.rn.f32x2 %0, %1, %2, %3;" : "=l"(d) : "l"(a), "l"(b), "l"(c)); return d;
}
__device__ __forceinline__ u64 add2(u64 a, u64 b) {
    u64 d; asm("add.rn.f32x2 %0, %1, %2;" : "=l"(d) : "l"(a), "l"(b)); return d;
}
__device__ __forceinline__ u64 mul2(u64 a, u64 b) {
    u64 d; asm("mul.rn.f32x2 %0, %1, %2;" : "=l"(d) : "l"(a), "l"(b)); return d;
}

__device__ __forceinline__ int eidx(const void* p, int e, int is64) {
    if (is64) return (int)__ldcs(((const long long*)p) + e);
    return __ldcs(((const int*)p) + e);
}

__device__ __forceinline__ void red_v4(float4* addr, float x, float y, float z, float w) {
    asm volatile("red.global.add.v4.f32 [%0], {%1, %2, %3, %4};"
                 :: "l"(addr), "f"(x), "f"(y), "f"(z), "f"(w) : "memory");
}

// ---------------- fused init: detect dtype + Wc/bc + zero everything --------
// Grid covers NN; block 0 additionally computes g_Wc/g_bc and g_is64.
__global__ void __launch_bounds__(256) k_init(const unsigned* __restrict__ srcw,
                                              const float* __restrict__ W2,
                                              const float* __restrict__ b2,
                                              const float* __restrict__ Wfc,
                                              const float* __restrict__ bfc) {
    int i = blockIdx.x * blockDim.x + threadIdx.x;
    if (i < NN) {
        g_deg_out[i] = 0;
        g_deg_in[i] = 0;
        float4 z = make_float4(0.f, 0.f, 0.f, 0.f);
        g_agg1[i * 4 + 0] = z;
        g_agg1[i * 4 + 1] = z;
        g_agg1[i * 4 + 2] = z;
        g_agg1[i * 4 + 3] = z;
        g_agg2[i] = z;
    }
    if (blockIdx.x == 0) {
        int t = threadIdx.x;
        if (t == 255) {  // index dtype detection: int64 idx < 1e5 -> odd words 0
            int is64 = 1;
            #pragma unroll 1
            for (int j = 0; j < 256; j++) {
                if (srcw[2 * j + 1] != 0u) { is64 = 0; break; }
            }
            g_is64 = is64;
        }
        if (t < H * NC) {
            int k = t / NC, c = t % NC;
            float s = 0.f;
            #pragma unroll 4
            for (int j = 0; j < FOUT; j++) s += W2[k * FOUT + j] * Wfc[j * NC + c];
            g_Wc[t] = s;
        }
        if (t >= 64 && t < 64 + NC) {
            int c = t - 64;
            float s = bfc[c];
            #pragma unroll 4
            for (int j = 0; j < FOUT; j++) s += b2[j] * Wfc[j * NC + c];
            g_bc[c] = s;
        }
    }
}

// ---------------- degrees ----------------
__global__ void k_degree(const void* __restrict__ src, const void* __restrict__ dst) {
    int e = blockIdx.x * blockDim.x + threadIdx.x;
    if (e >= NE) return;
    int is64 = g_is64;
    atomicAdd(&g_deg_out[eidx(src, e, is64)], 1);
    atomicAdd(&g_deg_in[eidx(dst, e, is64)], 1);
}

// ---------------- layer-1 GEMM: P1 = norm_src * (feat @ W1) -----------------
__global__ void __launch_bounds__(256) k_gemm1(const float* __restrict__ feat,
                                               const float* __restrict__ W1) {
    __shared__ float2 Wp[8 * FIN];  // [kk][i]
    for (int t = threadIdx.x; t < FIN * 8; t += 256) {
        int i = t >> 3, kk = t & 7;
        Wp[kk * FIN + i] = ((const float2*)W1)[t];  // (W1[i][2kk], W1[i][2kk+1])
    }
    __syncthreads();
    const u64* WpU = (const u64*)Wp;

    int warp = threadIdx.x >> 5, lane = threadIdx.x & 31;
    int row0 = (blockIdx.x * 8 + warp) * 4;
    if (row0 >= NN) return;

    u64 acc[4][8];
    #pragma unroll
    for (int r = 0; r < 4; r++)
        #pragma unroll
        for (int kk = 0; kk < 8; kk++) acc[r][kk] = 0ull;

    #pragma unroll
    for (int m = 0; m < 16; m++) {
        int i = lane + 32 * m;
        u64 wk[8];
        #pragma unroll
        for (int kk = 0; kk < 8; kk++) wk[kk] = WpU[kk * FIN + i];
        #pragma unroll
        for (int r = 0; r < 4; r++) {
            int row = row0 + r;
            float xv = (row < NN) ? __ldcs(feat + (size_t)row * FIN + i) : 0.f;
            u64 xx = pack2(xv, xv);
            #pragma unroll
            for (int kk = 0; kk < 8; kk++) acc[r][kk] = fma2(xx, wk[kk], acc[r][kk]);
        }
    }

    #pragma unroll
    for (int r = 0; r < 4; r++)
        #pragma unroll
        for (int kk = 0; kk < 8; kk++)
            #pragma unroll
            for (int off = 16; off > 0; off >>= 1)
                acc[r][kk] = add2(acc[r][kk], __shfl_xor_sync(0xffffffffu, acc[r][kk], off));

    if (lane == 0) {
        #pragma unroll
        for (int r = 0; r < 4; r++) {
            int row = row0 + r;
            if (row >= NN) break;
            float ns = rsqrtf(fmaxf((float)g_deg_out[row], 1.f));
            u64 nsp = pack2(ns, ns);
            #pragma unroll
            for (int c = 0; c < 4; c++) {
                float a, b, cc, d;
                unpack2(mul2(acc[r][2 * c + 0], nsp), a, b);
                unpack2(mul2(acc[r][2 * c + 1], nsp), cc, d);
                g_P1[row * 4 + c] = make_float4(a, b, cc, d);
            }
        }
    }
}

// ---------------- scatter pass 1: agg1[dst] += P1[src] (16 floats) -----------
__global__ void __launch_bounds__(256) k_scatter1(const void* __restrict__ src,
                                                  const void* __restrict__ dst) {
    int e = blockIdx.x * blockDim.x + threadIdx.x;
    if (e >= NE) return;
    int is64 = g_is64;
    int s = eidx(src, e, is64);
    int d = eidx(dst, e, is64);
    const float4* ps = (const float4*)g_P1 + s * 4;
    float4*       pd = g_agg1 + d * 4;
    #pragma unroll
    for (int c = 0; c < 4; c++) {
        float4 v = __ldg(ps + c);
        red_v4(pd + c, v.x, v.y, v.z, v.w);
    }
}

// ---------------- mid: Q2 = (relu(agg1*nd + b1)*ns) @ Wc ---------------------
__global__ void k_mid(const float* __restrict__ b1) {
    int n = blockIdx.x * blockDim.x + threadIdx.x;
    if (n >= NN) return;
    float nd = rsqrtf(fmaxf((float)g_deg_in[n], 1.f));
    float ns = rsqrtf(fmaxf((float)g_deg_out[n], 1.f));
    float o0 = 0.f, o1 = 0.f, o2 = 0.f;
    #pragma unroll
    for (int c = 0; c < 4; c++) {
        float4 a = g_agg1[n * 4 + c];
        float4 b = ((const float4*)b1)[c];
        float h0 = fmaxf(fmaf(a.x, nd, b.x), 0.f) * ns;
        float h1 = fmaxf(fmaf(a.y, nd, b.y), 0.f) * ns;
        float h2 = fmaxf(fmaf(a.z, nd, b.z), 0.f) * ns;
        float h3 = fmaxf(fmaf(a.w, nd, b.w), 0.f) * ns;
        int k = 4 * c;
        o0 = fmaf(h0, g_Wc[(k+0)*NC+0], fmaf(h1, g_Wc[(k+1)*NC+0],
             fmaf(h2, g_Wc[(k+2)*NC+0], fmaf(h3, g_Wc[(k+3)*NC+0], o0))));
        o1 = fmaf(h0, g_Wc[(k+0)*NC+1], fmaf(h1, g_Wc[(k+1)*NC+1],
             fmaf(h2, g_Wc[(k+2)*NC+1], fmaf(h3, g_Wc[(k+3)*NC+1], o1))));
        o2 = fmaf(h0, g_Wc[(k+0)*NC+2], fmaf(h1, g_Wc[(k+1)*NC+2],
             fmaf(h2, g_Wc[(k+2)*NC+2], fmaf(h3, g_Wc[(k+3)*NC+2], o2))));
    }
    g_Q2[n] = make_float4(o0, o1, o2, 0.f);
}

// ---------------- scatter pass 2: agg2[dst] += Q2[src]  (ONE v4 RED/edge) ----
__global__ void __launch_bounds__(256) k_scatter2(const void* __restrict__ src,
                                                  const void* __restrict__ dst) {
    int e = blockIdx.x * blockDim.x + threadIdx.x;
    if (e >= NE) return;
    int is64 = g_is64;
    int s = eidx(src, e, is64);
    int d = eidx(dst, e, is64);
    float4 v = __ldg(g_Q2 + s);
    red_v4(g_agg2 + d, v.x, v.y, v.z, v.w);
}

// ---------------- final: out = nd * agg2 + bc -------------------------------
__global__ void k_final(float* __restrict__ out) {
    int n = blockIdx.x * blockDim.x + threadIdx.x;
    if (n >= NN) return;
    float nd = rsqrtf(fmaxf((float)g_deg_in[n], 1.f));
    float4 a = g_agg2[n];
    out[n * 3 + 0] = fmaf(a.x, nd, g_bc[0]);
    out[n * 3 + 1] = fmaf(a.y, nd, g_bc[1]);
    out[n * 3 + 2] = fmaf(a.z, nd, g_bc[2]);
}

// ---------------- launch ----------------
extern "C" void kernel_launch(void* const* d_in, const int* in_sizes, int n_in,
                              void* d_out, int out_size) {
    const float* features = (const float*)d_in[0];
    const void*  src      = d_in[1];
    const void*  dst      = d_in[2];
    const float* W1       = (const float*)d_in[3];
    const float* b1       = (const float*)d_in[4];
    const float* W2       = (const float*)d_in[5];
    const float* b2       = (const float*)d_in[6];
    const float* Wfc      = (const float*)d_in[7];
    const float* bfc      = (const float*)d_in[8];
    float* out = (float*)d_out;

    (void)in_sizes; (void)n_in; (void)out_size;

    const int EB = (NE + 255) / 256;
    const int NB = (NN + 255) / 256;

    // node order chosen so k_scatter1 sits in the ncu capture slot (4th node)
    k_init<<<NB, 256>>>((const unsigned*)src, W2, b2, Wfc, bfc);  // 1
    k_degree<<<EB, 256>>>(src, dst);                              // 2
    k_gemm1<<<(NN + 31) / 32, 256>>>(features, W1);               // 3
    k_scatter1<<<EB, 256>>>(src, dst);                            // 4  <- profiled
    k_mid<<<NB, 256>>>(b1);                                       // 5
    k_scatter2<<<EB, 256>>>(src, dst);                            // 6
    k_final<<<NB, 256>>>(out);                                    // 7
}

// round 8
// speedup vs baseline: 1.6367x; 1.0501x over previous
#include <cuda_runtime.h>
#include <cstdint>

#define NN 100000
#define NE 3200000
#define FIN 512
#define H   16
#define FOUT 128
#define NC  3

// ---------------- scratch (no allocations allowed) ----------------
__device__ float4 g_P1[NN * 4];    // layer-1 projected RAW (no norm), 16 f/node
__device__ float4 g_agg1[NN * 4];  // layer-1 aggregation target
__device__ float4 g_Q2[NN];        // (relu(...)*ns) @ Wc : 3 floats + pad per node
__device__ float4 g_agg2[NN];      // layer-2 aggregation target (3 floats + pad)
__device__ int    g_deg_out[NN];
__device__ int    g_deg_in[NN];
__device__ float  g_Wc[H * NC];    // W2 @ Wfc  (16x3)
__device__ float  g_bc[NC];        // b2 @ Wfc + bfc
__device__ int    g_is64;

// ---------------- f32x2 packed math helpers ----------------
typedef unsigned long long u64;

__device__ __forceinline__ u64 pack2(float a, float b) {
    u64 r; asm("mov.b64 %0, {%1, %2};" : "=l"(r) : "f"(a), "f"(b)); return r;
}
__device__ __forceinline__ void unpack2(u64 v, float& a, float& b) {
    asm("mov.b64 {%0, %1}, %2;" : "=f"(a), "=f"(b) : "l"(v));
}
__device__ __forceinline__ u64 fma2(u64 a, u64 b, u64 c) {
    u64 d; asm("fma.rn.f32x2 %0, %1, %2, %3;" : "=l"(d) : "l"(a), "l"(b), "l"(c)); return d;
}
__device__ __forceinline__ u64 add2(u64 a, u64 b) {
    u64 d; asm("add.rn.f32x2 %0, %1, %2;" : "=l"(d) : "l"(a), "l"(b)); return d;
}

__device__ __forceinline__ int eidx(const void* p, int e, int is64) {
    if (is64) return (int)__ldcs(((const long long*)p) + e);
    return __ldcs(((const int*)p) + e);
}

__device__ __forceinline__ void red_v4(float4* addr, float x, float y, float z, float w) {
    asm volatile("red.global.add.v4.f32 [%0], {%1, %2, %3, %4};"
                 :: "l"(addr), "f"(x), "f"(y), "f"(z), "f"(w) : "memory");
}

// ---------------- init 0: detect dtype + fused W2@Wfc (1 block) --------------
__global__ void k_init0(const unsigned* __restrict__ srcw,
                        const float* __restrict__ W2, const float* __restrict__ b2,
                        const float* __restrict__ Wfc, const float* __restrict__ bfc) {
    int t = threadIdx.x;
    if (t == 255) {  // int64 idx < 1e5 -> every odd 32-bit word is 0
        int is64 = 1;
        #pragma unroll 1
        for (int j = 0; j < 256; j++) {
            if (srcw[2 * j + 1] != 0u) { is64 = 0; break; }
        }
        g_is64 = is64;
    }
    if (t < H * NC) {
        int k = t / NC, c = t % NC;
        float s = 0.f;
        #pragma unroll 4
        for (int j = 0; j < FOUT; j++) s += W2[k * FOUT + j] * Wfc[j * NC + c];
        g_Wc[t] = s;
    }
    if (t >= 64 && t < 64 + NC) {
        int c = t - 64;
        float s = bfc[c];
        #pragma unroll 4
        for (int j = 0; j < FOUT; j++) s += b2[j] * Wfc[j * NC + c];
        g_bc[c] = s;
    }
}

// ---------------- init 1: zero degrees + agg2 --------------------------------
__global__ void k_init1() {
    int i = blockIdx.x * blockDim.x + threadIdx.x;
    if (i < NN) {
        g_deg_out[i] = 0;
        g_deg_in[i] = 0;
        g_agg2[i] = make_float4(0.f, 0.f, 0.f, 0.f);
    }
}

// ---------------- init 2: zero agg1 ------------------------------------------
__global__ void k_init2() {
    int i = blockIdx.x * blockDim.x + threadIdx.x;
    if (i < NN * 4) g_agg1[i] = make_float4(0.f, 0.f, 0.f, 0.f);
}

// ---------------- FAT kernel: gemm1 (raw P1) blocks + degree blocks ----------
#define GEMM_B ((NN + 31) / 32)          // 3125 blocks, warp = 4 rows
#define EDGE_B ((NE + 255) / 256)        // 12500 blocks

__global__ void __launch_bounds__(256) k_fat(const float* __restrict__ feat,
                                             const float* __restrict__ W1,
                                             const void* __restrict__ src,
                                             const void* __restrict__ dst) {
    if (blockIdx.x >= GEMM_B) {
        // -------- degree role --------
        int e = (blockIdx.x - GEMM_B) * blockDim.x + threadIdx.x;
        if (e >= NE) return;
        int is64 = g_is64;
        atomicAdd(&g_deg_out[eidx(src, e, is64)], 1);
        atomicAdd(&g_deg_in[eidx(dst, e, is64)], 1);
        return;
    }

    // -------- gemm role: P1 = feat @ W1 (unscaled) --------
    __shared__ float2 Wp[8 * FIN];  // [kk][i]
    for (int t = threadIdx.x; t < FIN * 8; t += 256) {
        int i = t >> 3, kk = t & 7;
        Wp[kk * FIN + i] = ((const float2*)W1)[t];
    }
    __syncthreads();
    const u64* WpU = (const u64*)Wp;

    int warp = threadIdx.x >> 5, lane = threadIdx.x & 31;
    int row0 = (blockIdx.x * 8 + warp) * 4;
    if (row0 >= NN) return;

    u64 acc[4][8];
    #pragma unroll
    for (int r = 0; r < 4; r++)
        #pragma unroll
        for (int kk = 0; kk < 8; kk++) acc[r][kk] = 0ull;

    #pragma unroll
    for (int m = 0; m < 16; m++) {
        int i = lane + 32 * m;
        u64 wk[8];
        #pragma unroll
        for (int kk = 0; kk < 8; kk++) wk[kk] = WpU[kk * FIN + i];
        #pragma unroll
        for (int r = 0; r < 4; r++) {
            int row = row0 + r;
            float xv = (row < NN) ? __ldcs(feat + (size_t)row * FIN + i) : 0.f;
            u64 xx = pack2(xv, xv);
            #pragma unroll
            for (int kk = 0; kk < 8; kk++) acc[r][kk] = fma2(xx, wk[kk], acc[r][kk]);
        }
    }

    #pragma unroll
    for (int r = 0; r < 4; r++)
        #pragma unroll
        for (int kk = 0; kk < 8; kk++)
            #pragma unroll
            for (int off = 16; off > 0; off >>= 1)
                acc[r][kk] = add2(acc[r][kk], __shfl_xor_sync(0xffffffffu, acc[r][kk], off));

    if (lane == 0) {
        #pragma unroll
        for (int r = 0; r < 4; r++) {
            int row = row0 + r;
            if (row >= NN) break;
            #pragma unroll
            for (int c = 0; c < 4; c++) {
                float a, b, cc, d;
                unpack2(acc[r][2 * c + 0], a, b);
                unpack2(acc[r][2 * c + 1], cc, d);
                g_P1[row * 4 + c] = make_float4(a, b, cc, d);
            }
        }
    }
}

// ---------------- scatter 1: agg1[dst] += ns[src] * P1[src] ------------------
__global__ void __launch_bounds__(256) k_scatter1(const void* __restrict__ src,
                                                  const void* __restrict__ dst) {
    int e = blockIdx.x * blockDim.x + threadIdx.x;
    if (e >= NE) return;
    int is64 = g_is64;
    int s = eidx(src, e, is64);
    int d = eidx(dst, e, is64);
    float ns = rsqrtf(fmaxf((float)__ldg(&g_deg_out[s]), 1.f));
    const float4* ps = (const float4*)g_P1 + s * 4;
    float4*       pd = g_agg1 + d * 4;
    #pragma unroll
    for (int c = 0; c < 4; c++) {
        float4 v = __ldg(ps + c);
        red_v4(pd + c, v.x * ns, v.y * ns, v.z * ns, v.w * ns);
    }
}

// ---------------- mid: Q2 = (relu(agg1*nd + b1)*ns) @ Wc ---------------------
__global__ void k_mid(const float* __restrict__ b1) {
    int n = blockIdx.x * blockDim.x + threadIdx.x;
    if (n >= NN) return;
    float nd = rsqrtf(fmaxf((float)g_deg_in[n], 1.f));
    float ns = rsqrtf(fmaxf((float)g_deg_out[n], 1.f));
    float o0 = 0.f, o1 = 0.f, o2 = 0.f;
    #pragma unroll
    for (int c = 0; c < 4; c++) {
        float4 a = g_agg1[n * 4 + c];
        float4 b = ((const float4*)b1)[c];
        float h0 = fmaxf(fmaf(a.x, nd, b.x), 0.f) * ns;
        float h1 = fmaxf(fmaf(a.y, nd, b.y), 0.f) * ns;
        float h2 = fmaxf(fmaf(a.z, nd, b.z), 0.f) * ns;
        float h3 = fmaxf(fmaf(a.w, nd, b.w), 0.f) * ns;
        int k = 4 * c;
        o0 = fmaf(h0, g_Wc[(k+0)*NC+0], fmaf(h1, g_Wc[(k+1)*NC+0],
             fmaf(h2, g_Wc[(k+2)*NC+0], fmaf(h3, g_Wc[(k+3)*NC+0], o0))));
        o1 = fmaf(h0, g_Wc[(k+0)*NC+1], fmaf(h1, g_Wc[(k+1)*NC+1],
             fmaf(h2, g_Wc[(k+2)*NC+1], fmaf(h3, g_Wc[(k+3)*NC+1], o1))));
        o2 = fmaf(h0, g_Wc[(k+0)*NC+2], fmaf(h1, g_Wc[(k+1)*NC+2],
             fmaf(h2, g_Wc[(k+2)*NC+2], fmaf(h3, g_Wc[(k+3)*NC+2], o2))));
    }
    g_Q2[n] = make_float4(o0, o1, o2, 0.f);
}

// ---------------- scatter 2: agg2[dst] += Q2[src]  (ONE v4 RED/edge) ---------
__global__ void __launch_bounds__(256) k_scatter2(const void* __restrict__ src,
                                                  const void* __restrict__ dst) {
    int e = blockIdx.x * blockDim.x + threadIdx.x;
    if (e >= NE) return;
    int is64 = g_is64;
    int s = eidx(src, e, is64);
    int d = eidx(dst, e, is64);
    float4 v = __ldg(g_Q2 + s);
    red_v4(g_agg2 + d, v.x, v.y, v.z, v.w);
}

// ---------------- final: out = nd * agg2 + bc -------------------------------
__global__ void k_final(float* __restrict__ out) {
    int n = blockIdx.x * blockDim.x + threadIdx.x;
    if (n >= NN) return;
    float nd = rsqrtf(fmaxf((float)g_deg_in[n], 1.f));
    float4 a = g_agg2[n];
    out[n * 3 + 0] = fmaf(a.x, nd, g_bc[0]);
    out[n * 3 + 1] = fmaf(a.y, nd, g_bc[1]);
    out[n * 3 + 2] = fmaf(a.z, nd, g_bc[2]);
}

// ---------------- launch ----------------
extern "C" void kernel_launch(void* const* d_in, const int* in_sizes, int n_in,
                              void* d_out, int out_size) {
    const float* features = (const float*)d_in[0];
    const void*  src      = d_in[1];
    const void*  dst      = d_in[2];
    const float* W1       = (const float*)d_in[3];
    const float* b1       = (const float*)d_in[4];
    const float* W2       = (const float*)d_in[5];
    const float* b2       = (const float*)d_in[6];
    const float* Wfc      = (const float*)d_in[7];
    const float* bfc      = (const float*)d_in[8];
    float* out = (float*)d_out;

    (void)in_sizes; (void)n_in; (void)out_size;

    const int EB = EDGE_B;
    const int NB = (NN + 255) / 256;

    k_init0<<<1, 256>>>((const unsigned*)src, W2, b2, Wfc, bfc);   // 1
    k_init1<<<NB, 256>>>();                                        // 2
    k_init2<<<(NN * 4 + 255) / 256, 256>>>();                      // 3
    k_fat<<<GEMM_B + EDGE_B, 256>>>(features, W1, src, dst);       // 4 <- profiled
    k_scatter1<<<EB, 256>>>(src, dst);                             // 5
    k_mid<<<NB, 256>>>(b1);                                        // 6
    k_scatter2<<<EB, 256>>>(src, dst);                             // 7
    k_final<<<NB, 256>>>(out);                                     // 8
}